// round 3
// baseline (speedup 1.0000x reference)
#include <cuda_runtime.h>

#define N_NODES 50000
#define N_EDGES 625000
#define HID 128
#define KAN_HID 64
#define NB 9            /* 8 spline bases + silu as 9th */
#define K1 (HID*NB)     /* 1152 */

/* ------------------------------------------------------------------ */
/* scratch (device globals; no allocations allowed)                    */
/* ------------------------------------------------------------------ */
__device__ int   g_is64_nz;
__device__ int   g_is64;
__device__ int   g_src[N_EDGES];
__device__ int   g_dst[N_EDGES];
__device__ int   g_ssrc[N_EDGES];
__device__ int   g_cnt[N_NODES];
__device__ int   g_off[N_NODES + 1];
__device__ int   g_cur[N_NODES];
__device__ float g_agg[N_NODES * HID];
__device__ float g_h1[N_NODES * HID];
__device__ float g_h2[N_NODES * HID];
__device__ float g_hk[N_NODES * KAN_HID];
__device__ float g_phi[(size_t)N_NODES * K1];
__device__ float g_wc1[2 * HID * HID];   /* [k=0..255][c=0..127] */
__device__ float g_wc2[2 * HID * HID];
__device__ float g_wcat[K1 * KAN_HID];   /* [k=0..1151][o=0..63] */

/* grid value, matching jax: arange(-3, 9)*0.4 - 1 */
#define GRIDV(j) (0.4f * (float)((j) - 3) - 1.0f)

__device__ __forceinline__ void bspline_basis(float x, float* b /*[8]*/) {
    float t[11];
#pragma unroll
    for (int i = 0; i < 11; i++) {
        float g0 = GRIDV(i), g1 = GRIDV(i + 1);
        t[i] = (x >= g0 && x < g1) ? 1.0f : 0.0f;
    }
#pragma unroll
    for (int k = 1; k <= 3; k++) {
#pragma unroll
        for (int i = 0; i < 11; i++) {
            if (i < 11 - k) {
                float gi = GRIDV(i), gi1 = GRIDV(i + 1);
                float gik = GRIDV(i + k), gik1 = GRIDV(i + k + 1);
                t[i] = (x - gi) * (1.0f / (gik - gi)) * t[i]
                     + (gik1 - x) * (1.0f / (gik1 - gi1)) * t[i + 1];
            }
        }
    }
#pragma unroll
    for (int i = 0; i < 8; i++) b[i] = t[i];
}

__device__ __forceinline__ float silu_f(float x) {
    return x * (1.0f / (1.0f + __expf(-x)));
}

/* ------------------------------------------------------------------ */
/* edge preprocessing                                                  */
/* ------------------------------------------------------------------ */
__global__ void detect0_kernel() {
    if (threadIdx.x == 0) g_is64_nz = 0;
}

__global__ void detect_kernel(const int* __restrict__ e) {
    int i = blockIdx.x * blockDim.x + threadIdx.x;
    if (i < 2048 && e[2 * i + 1] != 0) atomicOr(&g_is64_nz, 1);
}

__global__ void detect2_kernel() {
    if (threadIdx.x == 0) g_is64 = (g_is64_nz == 0) ? 1 : 0;
}

__global__ void init_kernel() {
    int i = blockIdx.x * blockDim.x + threadIdx.x;
    if (i < N_NODES) g_cnt[i] = 0;
}

__global__ void convert_kernel(const int* __restrict__ e) {
    int i = blockIdx.x * blockDim.x + threadIdx.x;
    if (i >= N_EDGES) return;
    if (g_is64) {
        g_src[i] = e[2 * i];
        g_dst[i] = e[2 * N_EDGES + 2 * i];
    } else {
        g_src[i] = e[i];
        g_dst[i] = e[N_EDGES + i];
    }
}

__global__ void hist_kernel() {
    int i = blockIdx.x * blockDim.x + threadIdx.x;
    if (i < N_EDGES) atomicAdd(&g_cnt[g_dst[i]], 1);
}

__device__ __forceinline__ int warp_incl_scan(int v) {
#pragma unroll
    for (int d = 1; d < 32; d <<= 1) {
        int t = __shfl_up_sync(0xffffffffu, v, d);
        if ((threadIdx.x & 31) >= d) v += t;
    }
    return v;
}

__global__ void scan_kernel() {
    __shared__ int wsum[32];
    __shared__ int carry;
    int tid = threadIdx.x, lane = tid & 31, w = tid >> 5;
    if (tid == 0) carry = 0;
    __syncthreads();
    for (int base = 0; base < N_NODES; base += 1024) {
        int i = base + tid;
        int v = (i < N_NODES) ? g_cnt[i] : 0;
        int inc = warp_incl_scan(v);
        if (lane == 31) wsum[w] = inc;
        __syncthreads();
        if (w == 0) {
            int s = wsum[lane];
            s = warp_incl_scan(s);
            wsum[lane] = s;
        }
        __syncthreads();
        int woff = (w > 0) ? wsum[w - 1] : 0;
        int excl = carry + woff + inc - v;
        if (i < N_NODES) { g_off[i] = excl; g_cur[i] = excl; }
        int total = wsum[31];
        __syncthreads();
        if (tid == 0) carry += total;
        __syncthreads();
    }
    if (tid == 0) g_off[N_NODES] = carry;
}

__global__ void scatter_kernel() {
    int i = blockIdx.x * blockDim.x + threadIdx.x;
    if (i >= N_EDGES) return;
    int d = g_dst[i];
    int p = atomicAdd(&g_cur[d], 1);
    g_ssrc[p] = g_src[i];
}

/* ------------------------------------------------------------------ */
/* mean aggregation: one warp per node, CSR                            */
/* ------------------------------------------------------------------ */
__global__ void agg_kernel(const float* __restrict__ xext, int use_h1) {
    int gw = (blockIdx.x * blockDim.x + threadIdx.x) >> 5;
    if (gw >= N_NODES) return;
    const float* __restrict__ src = use_h1 ? g_h1 : xext;
    int lane = threadIdx.x & 31;
    int e0 = g_off[gw], e1 = g_off[gw + 1];
    float ax = 0.f, ay = 0.f, az = 0.f, aw = 0.f;
    for (int e = e0; e < e1; e++) {
        int s = g_ssrc[e];
        float4 v = __ldg((const float4*)(src + (size_t)s * HID) + lane);
        ax += v.x; ay += v.y; az += v.z; aw += v.w;
    }
    int c = e1 - e0;
    float inv = (c > 0) ? (1.0f / (float)c) : 0.0f;
    float4 r = make_float4(ax * inv, ay * inv, az * inv, aw * inv);
    ((float4*)(g_agg + (size_t)gw * HID))[lane] = r;
}

/* ------------------------------------------------------------------ */
/* weight layout prep                                                  */
/* ------------------------------------------------------------------ */
__global__ void prep_kernel(const float* __restrict__ W1l, const float* __restrict__ W1r,
                            const float* __restrict__ W2l, const float* __restrict__ W2r,
                            const float* __restrict__ kb1, const float* __restrict__ ks1) {
    int t = blockIdx.x * blockDim.x + threadIdx.x;
    if (t < 256 * 128) {
        int k = t >> 7, c = t & 127;
        g_wc1[t] = (k < 128) ? W1l[c * 128 + k] : W1r[c * 128 + (k - 128)];
        g_wc2[t] = (k < 128) ? W2l[c * 128 + k] : W2r[c * 128 + (k - 128)];
    }
    if (t < K1 * KAN_HID) {
        int k = t >> 6, o = t & 63;
        int i = k / NB, j = k % NB;
        g_wcat[t] = (j < 8) ? ks1[((size_t)o * 128 + i) * 8 + j] : kb1[o * 128 + i];
    }
}

/* ------------------------------------------------------------------ */
/* conv GEMM: out = relu([agg | A2] @ Wcat^T + b)                      */
/* BM=64, BN=128, BK=16, 256 threads, 8x4 register tile                */
/* ------------------------------------------------------------------ */
__global__ __launch_bounds__(256) void conv_gemm_kernel(const float* __restrict__ xext,
                                                        const float* __restrict__ bias,
                                                        int layer) {
    const float* __restrict__ A1 = g_agg;
    const float* __restrict__ A2 = layer ? g_h1 : xext;
    const float* __restrict__ W  = layer ? g_wc2 : g_wc1;
    float* outp     = layer ? g_h2 : g_h1;

    __shared__ float As[16][68];
    __shared__ float Bs[16][132];
    int tid = threadIdx.x;
    int m0 = blockIdx.x * 64;
    int lm = tid >> 2, lkq = (tid & 3) << 2;          /* A loader */
    int bkr = tid >> 5, bc = (tid & 31) << 2;         /* B loader */
    int cg = tid & 31, rg = tid >> 5;                 /* compute */
    int c0 = cg << 2, r0 = rg << 3;

    float acc[8][4];
#pragma unroll
    for (int r = 0; r < 8; r++)
#pragma unroll
        for (int c = 0; c < 4; c++) acc[r][c] = 0.0f;

    int gm_l = m0 + lm;
    bool okA = gm_l < N_NODES;

    for (int k0 = 0; k0 < 256; k0 += 16) {
        const float* Asrc = (k0 < 128) ? A1 : A2;
        float4 a = okA ? __ldg((const float4*)(Asrc + (size_t)gm_l * 128 + (k0 & 127) + lkq))
                       : make_float4(0.f, 0.f, 0.f, 0.f);
        As[lkq + 0][lm] = a.x; As[lkq + 1][lm] = a.y;
        As[lkq + 2][lm] = a.z; As[lkq + 3][lm] = a.w;
        const float* wp = W + (k0 + bkr) * 128 + bc;
        float4 w0 = __ldg((const float4*)wp);
        float4 w1 = __ldg((const float4*)(wp + 8 * 128));
        *(float4*)&Bs[bkr][bc] = w0;
        *(float4*)&Bs[bkr + 8][bc] = w1;
        __syncthreads();
#pragma unroll
        for (int kk = 0; kk < 16; kk++) {
            float4 b4  = *(const float4*)&Bs[kk][c0];
            float4 alo = *(const float4*)&As[kk][r0];
            float4 ahi = *(const float4*)&As[kk][r0 + 4];
            float av[8] = {alo.x, alo.y, alo.z, alo.w, ahi.x, ahi.y, ahi.z, ahi.w};
            float bv[4] = {b4.x, b4.y, b4.z, b4.w};
#pragma unroll
            for (int r = 0; r < 8; r++)
#pragma unroll
                for (int c = 0; c < 4; c++)
                    acc[r][c] = fmaf(av[r], bv[c], acc[r][c]);
        }
        __syncthreads();
    }

    float4 bb = __ldg((const float4*)(bias + c0));
#pragma unroll
    for (int r = 0; r < 8; r++) {
        int gm = m0 + r0 + r;
        if (gm < N_NODES) {
            float4 o;
            o.x = fmaxf(acc[r][0] + bb.x, 0.0f);
            o.y = fmaxf(acc[r][1] + bb.y, 0.0f);
            o.z = fmaxf(acc[r][2] + bb.z, 0.0f);
            o.w = fmaxf(acc[r][3] + bb.w, 0.0f);
            *(float4*)(outp + (size_t)gm * 128 + c0) = o;
        }
    }
}

/* ------------------------------------------------------------------ */
/* Phi materialization: phi[n][i*9 + j] = Bspline_j(h2[n][i]), j=8 -> silu */
/* ------------------------------------------------------------------ */
__global__ void phi_kernel() {
    int t = blockIdx.x * blockDim.x + threadIdx.x;
    if (t >= N_NODES * HID) return;
    float x = g_h2[t];
    int n = t >> 7, i = t & 127;
    float b[8];
    bspline_basis(x, b);
    float* p = g_phi + (size_t)n * K1 + i * NB;
#pragma unroll
    for (int j = 0; j < 8; j++) p[j] = b[j];
    p[8] = silu_f(x);
}

/* ------------------------------------------------------------------ */
/* KAN1 GEMM: hk = phi(50000x1152) @ wcat^T -> 50000x64                */
/* BM=128, BN=64, BK=16, 256 threads, 8x4 tile                         */
/* ------------------------------------------------------------------ */
__global__ __launch_bounds__(256) void kan1_gemm_kernel() {
    __shared__ float As[16][132];
    __shared__ float Bs[16][68];
    int tid = threadIdx.x;
    int m0 = blockIdx.x * 128;
    int lm = tid >> 1, lkh = (tid & 1) << 3;
    int bkr = tid >> 4, bc = (tid & 15) << 2;
    int cg = tid & 15, rg = tid >> 4;
    int c0 = cg << 2, r0 = rg << 3;

    float acc[8][4];
#pragma unroll
    for (int r = 0; r < 8; r++)
#pragma unroll
        for (int c = 0; c < 4; c++) acc[r][c] = 0.0f;

    int gm_l = m0 + lm;
    bool okA = gm_l < N_NODES;
    const float* aprow = g_phi + (size_t)gm_l * K1;

    for (int k0 = 0; k0 < K1; k0 += 16) {
        float4 a0 = okA ? __ldg((const float4*)(aprow + k0 + lkh))
                        : make_float4(0.f, 0.f, 0.f, 0.f);
        float4 a1 = okA ? __ldg((const float4*)(aprow + k0 + lkh + 4))
                        : make_float4(0.f, 0.f, 0.f, 0.f);
        As[lkh + 0][lm] = a0.x; As[lkh + 1][lm] = a0.y;
        As[lkh + 2][lm] = a0.z; As[lkh + 3][lm] = a0.w;
        As[lkh + 4][lm] = a1.x; As[lkh + 5][lm] = a1.y;
        As[lkh + 6][lm] = a1.z; As[lkh + 7][lm] = a1.w;
        float4 w0 = __ldg((const float4*)(g_wcat + (k0 + bkr) * 64 + bc));
        *(float4*)&Bs[bkr][bc] = w0;
        __syncthreads();
#pragma unroll
        for (int kk = 0; kk < 16; kk++) {
            float4 b4  = *(const float4*)&Bs[kk][c0];
            float4 alo = *(const float4*)&As[kk][r0];
            float4 ahi = *(const float4*)&As[kk][r0 + 4];
            float av[8] = {alo.x, alo.y, alo.z, alo.w, ahi.x, ahi.y, ahi.z, ahi.w};
            float bv[4] = {b4.x, b4.y, b4.z, b4.w};
#pragma unroll
            for (int r = 0; r < 8; r++)
#pragma unroll
                for (int c = 0; c < 4; c++)
                    acc[r][c] = fmaf(av[r], bv[c], acc[r][c]);
        }
        __syncthreads();
    }

#pragma unroll
    for (int r = 0; r < 8; r++) {
        int gm = m0 + r0 + r;
        if (gm < N_NODES) {
            float4 o = make_float4(acc[r][0], acc[r][1], acc[r][2], acc[r][3]);
            *(float4*)(g_hk + (size_t)gm * 64 + c0) = o;
        }
    }
}

/* ------------------------------------------------------------------ */
/* KAN2: out[n][o] = sum_i basis(hk[n][i]) . w  (o = 0..1)             */
/* ------------------------------------------------------------------ */
__global__ __launch_bounds__(128) void kan2_kernel(const float* __restrict__ kb2,
                                                   const float* __restrict__ ks2,
                                                   float* __restrict__ out) {
    __shared__ float s_h[128 * 65];
    __shared__ float s_w[64 * 18];   /* [i][j(0..8)][o(0..1)] */
    int tid = threadIdx.x;
    for (int t = tid; t < 64 * 18; t += 128) {
        int i = t / 18, rem = t % 18, j = rem >> 1, o = rem & 1;
        s_w[t] = (j < 8) ? ks2[((size_t)o * 64 + i) * 8 + j] : kb2[o * 64 + i];
    }
    int n0 = blockIdx.x * 128;
    for (int t = tid; t < 128 * 64; t += 128) {
        int r = t >> 6, c = t & 63;
        int gn = n0 + r;
        s_h[r * 65 + c] = (gn < N_NODES) ? g_hk[(size_t)gn * 64 + c] : 0.0f;
    }
    __syncthreads();
    int gn = n0 + tid;
    if (gn >= N_NODES) return;
    float o0 = 0.0f, o1 = 0.0f;
    for (int i = 0; i < 64; i++) {
        float x = s_h[tid * 65 + i];
        float b[8];
        bspline_basis(x, b);
        float v8 = silu_f(x);
        const float* w = &s_w[i * 18];
#pragma unroll
        for (int j = 0; j < 8; j++) {
            o0 = fmaf(b[j], w[j * 2 + 0], o0);
            o1 = fmaf(b[j], w[j * 2 + 1], o1);
        }
        o0 = fmaf(v8, w[16], o0);
        o1 = fmaf(v8, w[17], o1);
    }
    out[(size_t)gn * 2 + 0] = o0;
    out[(size_t)gn * 2 + 1] = o1;
}

/* ------------------------------------------------------------------ */
extern "C" void kernel_launch(void* const* d_in, const int* in_sizes, int n_in,
                              void* d_out, int out_size) {
    const float* x   = (const float*)d_in[0];
    const int*   e   = (const int*)d_in[1];
    const float* W1l = (const float*)d_in[2];
    const float* b1  = (const float*)d_in[3];
    const float* W1r = (const float*)d_in[4];
    const float* W2l = (const float*)d_in[5];
    const float* b2  = (const float*)d_in[6];
    const float* W2r = (const float*)d_in[7];
    const float* kb1 = (const float*)d_in[8];
    const float* ks1 = (const float*)d_in[9];
    const float* kb2 = (const float*)d_in[10];
    const float* ks2 = (const float*)d_in[11];
    float* out = (float*)d_out;

    (void)in_sizes; (void)n_in; (void)out_size;

    const int EB = (N_EDGES + 255) / 256;     /* 2442 */
    const int NBK = (N_NODES + 255) / 256;    /* 196 */

    detect0_kernel<<<1, 32>>>();
    detect_kernel<<<8, 256>>>(e);
    detect2_kernel<<<1, 32>>>();
    init_kernel<<<NBK, 256>>>();
    convert_kernel<<<EB, 256>>>(e);
    hist_kernel<<<EB, 256>>>();
    scan_kernel<<<1, 1024>>>();
    scatter_kernel<<<EB, 256>>>();
    prep_kernel<<<(K1 * KAN_HID + 255) / 256, 256>>>(W1l, W1r, W2l, W2r, kb1, ks1);

    /* layer 1 */
    agg_kernel<<<(N_NODES + 7) / 8, 256>>>(x, 0);
    conv_gemm_kernel<<<(N_NODES + 63) / 64, 256>>>(x, b1, 0);
    /* layer 2 */
    agg_kernel<<<(N_NODES + 7) / 8, 256>>>(x, 1);
    conv_gemm_kernel<<<(N_NODES + 63) / 64, 256>>>(x, b2, 1);
    /* KAN 1 */
    phi_kernel<<<(N_NODES * HID + 255) / 256, 256>>>();
    kan1_gemm_kernel<<<(N_NODES + 127) / 128, 256>>>();
    /* KAN 2 */
    kan2_kernel<<<(N_NODES + 127) / 128, 128>>>(kb2, ks2, out);
}

// round 4
// speedup vs baseline: 1.1387x; 1.1387x over previous
#include <cuda_runtime.h>
#include <cuda_bf16.h>

#define N_NODES 50000
#define N_EDGES 625000
#define HID 128
#define KAN_HID 64
#define NB 9            /* 8 spline bases + silu as 9th */
#define K1 (HID*NB)     /* 1152 */
#define K1W (K1/2)      /* 576 packed words per phi row */

typedef unsigned int u32;

/* ------------------------------------------------------------------ */
/* scratch (device globals; no allocations allowed)                    */
/* ------------------------------------------------------------------ */
__device__ int   g_is64_nz;
__device__ int   g_is64;
__device__ int   g_src[N_EDGES];
__device__ int   g_dst[N_EDGES];
__device__ int   g_ssrc[N_EDGES];
__device__ int   g_cnt[N_NODES];
__device__ int   g_off[N_NODES + 1];
__device__ int   g_cur[N_NODES];
__device__ float g_h1[N_NODES * HID];
__device__ float g_h2[N_NODES * HID];
__device__ float g_hk[N_NODES * KAN_HID];
/* packed bf16 (2 per u32), hi/lo split operands */
__device__ u32 g_aggh[N_NODES * 64], g_aggl[N_NODES * 64];
__device__ u32 g_xh[N_NODES * 64],   g_xl[N_NODES * 64];
__device__ u32 g_h1h[N_NODES * 64],  g_h1l[N_NODES * 64];
__device__ u32 g_phih[(size_t)N_NODES * K1W], g_phil[(size_t)N_NODES * K1W];
__device__ u32 g_w1h[HID * HID], g_w1l[HID * HID];     /* [c][128 words of k] */
__device__ u32 g_w2h[HID * HID], g_w2l[HID * HID];
__device__ u32 g_wch[KAN_HID * K1W], g_wcl[KAN_HID * K1W]; /* [o][576 words] */

/* grid value, matching jax: arange(-3, 9)*0.4 - 1 */
#define GRIDV(j) (0.4f * (float)((j) - 3) - 1.0f)

__device__ __forceinline__ void bspline_basis(float x, float* b /*[8]*/) {
    float t[11];
#pragma unroll
    for (int i = 0; i < 11; i++) {
        float g0 = GRIDV(i), g1 = GRIDV(i + 1);
        t[i] = (x >= g0 && x < g1) ? 1.0f : 0.0f;
    }
#pragma unroll
    for (int k = 1; k <= 3; k++) {
#pragma unroll
        for (int i = 0; i < 11; i++) {
            if (i < 11 - k) {
                float gi = GRIDV(i), gi1 = GRIDV(i + 1);
                float gik = GRIDV(i + k), gik1 = GRIDV(i + k + 1);
                t[i] = (x - gi) * (1.0f / (gik - gi)) * t[i]
                     + (gik1 - x) * (1.0f / (gik1 - gi1)) * t[i + 1];
            }
        }
    }
#pragma unroll
    for (int i = 0; i < 8; i++) b[i] = t[i];
}

__device__ __forceinline__ float silu_f(float x) {
    return x * (1.0f / (1.0f + __expf(-x)));
}

__device__ __forceinline__ u32 pack2(float a, float b) {
    __nv_bfloat162 t = __floats2bfloat162_rn(a, b);
    return *reinterpret_cast<u32*>(&t);
}
__device__ __forceinline__ void split2(float a, float b, u32& hi, u32& lo) {
    __nv_bfloat16 ah = __float2bfloat16(a), bh = __float2bfloat16(b);
    float ar = a - __bfloat162float(ah);
    float br = b - __bfloat162float(bh);
    __nv_bfloat162 h; h.x = ah; h.y = bh;
    hi = *reinterpret_cast<u32*>(&h);
    lo = pack2(ar, br);
}

#define MMA16816(d, a, b0, b1)                                              \
    asm volatile("mma.sync.aligned.m16n8k16.row.col.f32.bf16.bf16.f32 "     \
                 "{%0,%1,%2,%3}, {%4,%5,%6,%7}, {%8,%9}, {%0,%1,%2,%3};\n"  \
                 : "+f"((d)[0]), "+f"((d)[1]), "+f"((d)[2]), "+f"((d)[3])   \
                 : "r"((a)[0]), "r"((a)[1]), "r"((a)[2]), "r"((a)[3]),      \
                   "r"(b0), "r"(b1))

/* ------------------------------------------------------------------ */
/* edge preprocessing                                                  */
/* ------------------------------------------------------------------ */
__global__ void detect0_kernel() { if (threadIdx.x == 0) g_is64_nz = 0; }

__global__ void detect_kernel(const int* __restrict__ e) {
    int i = blockIdx.x * blockDim.x + threadIdx.x;
    if (i < 2048 && e[2 * i + 1] != 0) atomicOr(&g_is64_nz, 1);
}

__global__ void detect2_kernel() {
    if (threadIdx.x == 0) g_is64 = (g_is64_nz == 0) ? 1 : 0;
}

__global__ void init_kernel() {
    int i = blockIdx.x * blockDim.x + threadIdx.x;
    if (i < N_NODES) g_cnt[i] = 0;
}

__global__ void convert_kernel(const int* __restrict__ e) {
    int i = blockIdx.x * blockDim.x + threadIdx.x;
    if (i >= N_EDGES) return;
    if (g_is64) {
        g_src[i] = e[2 * i];
        g_dst[i] = e[2 * N_EDGES + 2 * i];
    } else {
        g_src[i] = e[i];
        g_dst[i] = e[N_EDGES + i];
    }
}

__global__ void hist_kernel() {
    int i = blockIdx.x * blockDim.x + threadIdx.x;
    if (i < N_EDGES) atomicAdd(&g_cnt[g_dst[i]], 1);
}

__device__ __forceinline__ int warp_incl_scan(int v) {
#pragma unroll
    for (int d = 1; d < 32; d <<= 1) {
        int t = __shfl_up_sync(0xffffffffu, v, d);
        if ((threadIdx.x & 31) >= d) v += t;
    }
    return v;
}

__global__ void scan_kernel() {
    __shared__ int wsum[32];
    __shared__ int carry;
    int tid = threadIdx.x, lane = tid & 31, w = tid >> 5;
    if (tid == 0) carry = 0;
    __syncthreads();
    for (int base = 0; base < N_NODES; base += 1024) {
        int i = base + tid;
        int v = (i < N_NODES) ? g_cnt[i] : 0;
        int inc = warp_incl_scan(v);
        if (lane == 31) wsum[w] = inc;
        __syncthreads();
        if (w == 0) {
            int s = wsum[lane];
            s = warp_incl_scan(s);
            wsum[lane] = s;
        }
        __syncthreads();
        int woff = (w > 0) ? wsum[w - 1] : 0;
        int excl = carry + woff + inc - v;
        if (i < N_NODES) { g_off[i] = excl; g_cur[i] = excl; }
        int total = wsum[31];
        __syncthreads();
        if (tid == 0) carry += total;
        __syncthreads();
    }
    if (tid == 0) g_off[N_NODES] = carry;
}

__global__ void scatter_kernel() {
    int i = blockIdx.x * blockDim.x + threadIdx.x;
    if (i >= N_EDGES) return;
    int d = g_dst[i];
    int p = atomicAdd(&g_cur[d], 1);
    g_ssrc[p] = g_src[i];
}

/* ------------------------------------------------------------------ */
/* mean aggregation: one warp per node, CSR; emits bf16 hi/lo          */
/* ------------------------------------------------------------------ */
__global__ void agg_kernel(const float* __restrict__ xext, int use_h1) {
    int gw = (blockIdx.x * blockDim.x + threadIdx.x) >> 5;
    if (gw >= N_NODES) return;
    const float* __restrict__ src = use_h1 ? g_h1 : xext;
    int lane = threadIdx.x & 31;
    int e0 = g_off[gw], e1 = g_off[gw + 1];
    float ax = 0.f, ay = 0.f, az = 0.f, aw = 0.f;
    for (int e = e0; e < e1; e++) {
        int s = g_ssrc[e];
        float4 v = __ldg((const float4*)(src + (size_t)s * HID) + lane);
        ax += v.x; ay += v.y; az += v.z; aw += v.w;
    }
    int c = e1 - e0;
    float inv = (c > 0) ? (1.0f / (float)c) : 0.0f;
    ax *= inv; ay *= inv; az *= inv; aw *= inv;
    u32 h0, l0, h1v, l1v;
    split2(ax, ay, h0, l0);
    split2(az, aw, h1v, l1v);
    size_t w0 = (size_t)gw * 64 + lane * 2;
    g_aggh[w0] = h0; g_aggh[w0 + 1] = h1v;
    g_aggl[w0] = l0; g_aggl[w0 + 1] = l1v;
}

/* ------------------------------------------------------------------ */
/* weight / input conversion                                           */
/* ------------------------------------------------------------------ */
__global__ void xcnv_kernel(const float* __restrict__ x) {
    int w = blockIdx.x * blockDim.x + threadIdx.x;
    if (w >= N_NODES * 64) return;
    float2 v = ((const float2*)x)[w];
    split2(v.x, v.y, g_xh[w], g_xl[w]);
}

__global__ void prep_w_kernel(const float* __restrict__ W1l, const float* __restrict__ W1r,
                              const float* __restrict__ W2l, const float* __restrict__ W2r) {
    int t = blockIdx.x * blockDim.x + threadIdx.x;
    if (t >= HID * HID) return;
    int c = t >> 7, w = t & 127;
    int k0 = 2 * w, k1 = k0 + 1;
    float v0 = (k0 < 128) ? W1l[c * 128 + k0] : W1r[c * 128 + k0 - 128];
    float v1 = (k1 < 128) ? W1l[c * 128 + k1] : W1r[c * 128 + k1 - 128];
    split2(v0, v1, g_w1h[t], g_w1l[t]);
    v0 = (k0 < 128) ? W2l[c * 128 + k0] : W2r[c * 128 + k0 - 128];
    v1 = (k1 < 128) ? W2l[c * 128 + k1] : W2r[c * 128 + k1 - 128];
    split2(v0, v1, g_w2h[t], g_w2l[t]);
}

__global__ void prep_wc_kernel(const float* __restrict__ kb1, const float* __restrict__ ks1) {
    int t = blockIdx.x * blockDim.x + threadIdx.x;
    if (t >= KAN_HID * K1W) return;
    int o = t / K1W, w = t % K1W;
    int k0 = 2 * w, k1 = k0 + 1;
    int i0 = k0 / NB, j0 = k0 % NB;
    int i1 = k1 / NB, j1 = k1 % NB;
    float v0 = (j0 < 8) ? ks1[((size_t)o * 128 + i0) * 8 + j0] : kb1[o * 128 + i0];
    float v1 = (j1 < 8) ? ks1[((size_t)o * 128 + i1) * 8 + j1] : kb1[o * 128 + i1];
    split2(v0, v1, g_wch[t], g_wcl[t]);
}

/* ------------------------------------------------------------------ */
/* conv GEMM (tensor core): out = relu([agg | A2] @ W^T + b)           */
/* BM=128 BN=64 BK=32, 8 warps (4m x 2n), warp 32x32, bf16 split 3-mma */
/* ------------------------------------------------------------------ */
__global__ __launch_bounds__(256) void conv_mma_kernel(const float* __restrict__ bias,
                                                       int layer) {
    __shared__ u32 AsH[128][20], AsL[128][20], BsH[64][20], BsL[64][20];

    const u32* __restrict__ Ah1 = g_aggh;
    const u32* __restrict__ Al1 = g_aggl;
    const u32* __restrict__ Ah2 = layer ? g_h1h : g_xh;
    const u32* __restrict__ Al2 = layer ? g_h1l : g_xl;
    const u32* __restrict__ Wh  = layer ? g_w2h : g_w1h;
    const u32* __restrict__ Wl  = layer ? g_w2l : g_w1l;
    float* outp = layer ? g_h2 : g_h1;

    int tid = threadIdx.x;
    int m0 = blockIdx.x * 128;
    int nblk = blockIdx.y * 64;

    int arow = tid >> 1, aw = (tid & 1) * 8;
    int brow = tid >> 2, bw = (tid & 3) * 4;
    int gmA = m0 + arow;
    bool okA = gmA < N_NODES;

    int lane = tid & 31, grp = lane >> 2, tig = lane & 3;
    int wid = tid >> 5;
    int mrow0 = (wid & 3) * 32, ncol0 = (wid >> 2) * 32;

    float acc[2][4][4];
#pragma unroll
    for (int mt = 0; mt < 2; mt++)
#pragma unroll
        for (int nt = 0; nt < 4; nt++)
#pragma unroll
            for (int q = 0; q < 4; q++) acc[mt][nt][q] = 0.0f;

    uint4 rAh0, rAh1, rAl0, rAl1, rBh, rBl;
    uint4 z4 = make_uint4(0, 0, 0, 0);
    {
        if (okA) {
            const uint4* p = (const uint4*)(Ah1 + (size_t)gmA * 64 + aw);
            rAh0 = p[0]; rAh1 = p[1];
            const uint4* q = (const uint4*)(Al1 + (size_t)gmA * 64 + aw);
            rAl0 = q[0]; rAl1 = q[1];
        } else { rAh0 = rAh1 = rAl0 = rAl1 = z4; }
        size_t bo = (size_t)(nblk + brow) * 128 + bw;
        rBh = *(const uint4*)(Wh + bo);
        rBl = *(const uint4*)(Wl + bo);
    }

    for (int s = 0; s < 8; s++) {
        __syncthreads();
        *(uint4*)&AsH[arow][aw]     = rAh0; *(uint4*)&AsH[arow][aw + 4] = rAh1;
        *(uint4*)&AsL[arow][aw]     = rAl0; *(uint4*)&AsL[arow][aw + 4] = rAl1;
        *(uint4*)&BsH[brow][bw]     = rBh;  *(uint4*)&BsL[brow][bw]     = rBl;
        __syncthreads();
        if (s < 7) {
            int k0 = (s + 1) * 32;
            const u32* Ah = (k0 < 128) ? Ah1 : Ah2;
            const u32* Al = (k0 < 128) ? Al1 : Al2;
            int awo = ((k0 & 127) >> 1) + aw;
            if (okA) {
                const uint4* p = (const uint4*)(Ah + (size_t)gmA * 64 + awo);
                rAh0 = p[0]; rAh1 = p[1];
                const uint4* q = (const uint4*)(Al + (size_t)gmA * 64 + awo);
                rAl0 = q[0]; rAl1 = q[1];
            } else { rAh0 = rAh1 = rAl0 = rAl1 = z4; }
            size_t bo = (size_t)(nblk + brow) * 128 + (k0 >> 1) + bw;
            rBh = *(const uint4*)(Wh + bo);
            rBl = *(const uint4*)(Wl + bo);
        }
#pragma unroll
        for (int kk = 0; kk < 2; kk++) {
            int wb = kk * 8;
            u32 aH[2][4], aL[2][4];
#pragma unroll
            for (int mt = 0; mt < 2; mt++) {
                int rb = mrow0 + mt * 16 + grp;
                aH[mt][0] = AsH[rb][wb + tig];     aH[mt][1] = AsH[rb + 8][wb + tig];
                aH[mt][2] = AsH[rb][wb + tig + 4]; aH[mt][3] = AsH[rb + 8][wb + tig + 4];
                aL[mt][0] = AsL[rb][wb + tig];     aL[mt][1] = AsL[rb + 8][wb + tig];
                aL[mt][2] = AsL[rb][wb + tig + 4]; aL[mt][3] = AsL[rb + 8][wb + tig + 4];
            }
#pragma unroll
            for (int nt = 0; nt < 4; nt++) {
                int nb = ncol0 + nt * 8 + grp;
                u32 bh0 = BsH[nb][wb + tig], bh1 = BsH[nb][wb + tig + 4];
                u32 bl0 = BsL[nb][wb + tig], bl1 = BsL[nb][wb + tig + 4];
#pragma unroll
                for (int mt = 0; mt < 2; mt++) {
                    MMA16816(acc[mt][nt], aH[mt], bh0, bh1);
                    MMA16816(acc[mt][nt], aL[mt], bh0, bh1);
                    MMA16816(acc[mt][nt], aH[mt], bl0, bl1);
                }
            }
        }
    }

#pragma unroll
    for (int mt = 0; mt < 2; mt++) {
#pragma unroll
        for (int nt = 0; nt < 4; nt++) {
            int col = nblk + ncol0 + nt * 8 + 2 * tig;
            float bx = __ldg(bias + col), by = __ldg(bias + col + 1);
            int r0 = m0 + mrow0 + mt * 16 + grp;
            if (r0 < N_NODES) {
                float v0 = fmaxf(acc[mt][nt][0] + bx, 0.0f);
                float v1 = fmaxf(acc[mt][nt][1] + by, 0.0f);
                float2 o = make_float2(v0, v1);
                *(float2*)&outp[(size_t)r0 * 128 + col] = o;
                if (layer == 0) {
                    u32 h, l; split2(v0, v1, h, l);
                    g_h1h[(size_t)r0 * 64 + (col >> 1)] = h;
                    g_h1l[(size_t)r0 * 64 + (col >> 1)] = l;
                }
            }
            int r1 = r0 + 8;
            if (r1 < N_NODES) {
                float v0 = fmaxf(acc[mt][nt][2] + bx, 0.0f);
                float v1 = fmaxf(acc[mt][nt][3] + by, 0.0f);
                float2 o = make_float2(v0, v1);
                *(float2*)&outp[(size_t)r1 * 128 + col] = o;
                if (layer == 0) {
                    u32 h, l; split2(v0, v1, h, l);
                    g_h1h[(size_t)r1 * 64 + (col >> 1)] = h;
                    g_h1l[(size_t)r1 * 64 + (col >> 1)] = l;
                }
            }
        }
    }
}

/* ------------------------------------------------------------------ */
/* Phi materialization in bf16 hi/lo: 2 features per thread (9 words)  */
/* ------------------------------------------------------------------ */
__global__ void phi_kernel() {
    int t = blockIdx.x * blockDim.x + threadIdx.x;
    if (t >= N_NODES * 64) return;
    int n = t >> 6, ip = t & 63;
    float x0 = g_h2[(size_t)n * 128 + 2 * ip];
    float x1 = g_h2[(size_t)n * 128 + 2 * ip + 1];
    float v[18];
    bspline_basis(x0, v);      v[8]  = silu_f(x0);
    bspline_basis(x1, v + 9);  v[17] = silu_f(x1);
    u32* ph = g_phih + (size_t)n * K1W + ip * 9;
    u32* pl = g_phil + (size_t)n * K1W + ip * 9;
#pragma unroll
    for (int w = 0; w < 9; w++) {
        u32 h, l;
        split2(v[2 * w], v[2 * w + 1], h, l);
        ph[w] = h; pl[w] = l;
    }
}

/* ------------------------------------------------------------------ */
/* KAN1 GEMM (tensor core): hk = phi(50000x1152) @ wcat^T -> 50000x64  */
/* ------------------------------------------------------------------ */
__global__ __launch_bounds__(256) void kan1_mma_kernel() {
    __shared__ u32 AsH[128][20], AsL[128][20], BsH[64][20], BsL[64][20];

    int tid = threadIdx.x;
    int m0 = blockIdx.x * 128;

    int arow = tid >> 1, aw = (tid & 1) * 8;
    int brow = tid >> 2, bw = (tid & 3) * 4;
    int gmA = m0 + arow;
    bool okA = gmA < N_NODES;

    int lane = tid & 31, grp = lane >> 2, tig = lane & 3;
    int wid = tid >> 5;
    int mrow0 = (wid & 3) * 32, ncol0 = (wid >> 2) * 32;

    float acc[2][4][4];
#pragma unroll
    for (int mt = 0; mt < 2; mt++)
#pragma unroll
        for (int nt = 0; nt < 4; nt++)
#pragma unroll
            for (int q = 0; q < 4; q++) acc[mt][nt][q] = 0.0f;

    uint4 rAh0, rAh1, rAl0, rAl1, rBh, rBl;
    uint4 z4 = make_uint4(0, 0, 0, 0);
    {
        if (okA) {
            const uint4* p = (const uint4*)(g_phih + (size_t)gmA * K1W + aw);
            rAh0 = p[0]; rAh1 = p[1];
            const uint4* q = (const uint4*)(g_phil + (size_t)gmA * K1W + aw);
            rAl0 = q[0]; rAl1 = q[1];
        } else { rAh0 = rAh1 = rAl0 = rAl1 = z4; }
        size_t bo = (size_t)brow * K1W + bw;
        rBh = *(const uint4*)(g_wch + bo);
        rBl = *(const uint4*)(g_wcl + bo);
    }

    const int S = K1 / 32;  /* 36 */
    for (int s = 0; s < S; s++) {
        __syncthreads();
        *(uint4*)&AsH[arow][aw]     = rAh0; *(uint4*)&AsH[arow][aw + 4] = rAh1;
        *(uint4*)&AsL[arow][aw]     = rAl0; *(uint4*)&AsL[arow][aw + 4] = rAl1;
        *(uint4*)&BsH[brow][bw]     = rBh;  *(uint4*)&BsL[brow][bw]     = rBl;
        __syncthreads();
        if (s < S - 1) {
            int kw = (s + 1) * 16;  /* word offset */
            if (okA) {
                const uint4* p = (const uint4*)(g_phih + (size_t)gmA * K1W + kw + aw);
                rAh0 = p[0]; rAh1 = p[1];
                const uint4* q = (const uint4*)(g_phil + (size_t)gmA * K1W + kw + aw);
                rAl0 = q[0]; rAl1 = q[1];
            } else { rAh0 = rAh1 = rAl0 = rAl1 = z4; }
            size_t bo = (size_t)brow * K1W + kw + bw;
            rBh = *(const uint4*)(g_wch + bo);
            rBl = *(const uint4*)(g_wcl + bo);
        }
#pragma unroll
        for (int kk = 0; kk < 2; kk++) {
            int wb = kk * 8;
            u32 aH[2][4], aL[2][4];
#pragma unroll
            for (int mt = 0; mt < 2; mt++) {
                int rb = mrow0 + mt * 16 + grp;
                aH[mt][0] = AsH[rb][wb + tig];     aH[mt][1] = AsH[rb + 8][wb + tig];
                aH[mt][2] = AsH[rb][wb + tig + 4]; aH[mt][3] = AsH[rb + 8][wb + tig + 4];
                aL[mt][0] = AsL[rb][wb + tig];     aL[mt][1] = AsL[rb + 8][wb + tig];
                aL[mt][2] = AsL[rb][wb + tig + 4]; aL[mt][3] = AsL[rb + 8][wb + tig + 4];
            }
#pragma unroll
            for (int nt = 0; nt < 4; nt++) {
                int nb = ncol0 + nt * 8 + grp;
                u32 bh0 = BsH[nb][wb + tig], bh1 = BsH[nb][wb + tig + 4];
                u32 bl0 = BsL[nb][wb + tig], bl1 = BsL[nb][wb + tig + 4];
#pragma unroll
                for (int mt = 0; mt < 2; mt++) {
                    MMA16816(acc[mt][nt], aH[mt], bh0, bh1);
                    MMA16816(acc[mt][nt], aL[mt], bh0, bh1);
                    MMA16816(acc[mt][nt], aH[mt], bl0, bl1);
                }
            }
        }
    }

#pragma unroll
    for (int mt = 0; mt < 2; mt++) {
#pragma unroll
        for (int nt = 0; nt < 4; nt++) {
            int col = ncol0 + nt * 8 + 2 * tig;
            int r0 = m0 + mrow0 + mt * 16 + grp;
            if (r0 < N_NODES) {
                float2 o = make_float2(acc[mt][nt][0], acc[mt][nt][1]);
                *(float2*)&g_hk[(size_t)r0 * 64 + col] = o;
            }
            int r1 = r0 + 8;
            if (r1 < N_NODES) {
                float2 o = make_float2(acc[mt][nt][2], acc[mt][nt][3]);
                *(float2*)&g_hk[(size_t)r1 * 64 + col] = o;
            }
        }
    }
}

/* ------------------------------------------------------------------ */
/* KAN2: out[n][o] = sum_i basis(hk[n][i]) . w  (o = 0..1)             */
/* ------------------------------------------------------------------ */
__global__ __launch_bounds__(128) void kan2_kernel(const float* __restrict__ kb2,
                                                   const float* __restrict__ ks2,
                                                   float* __restrict__ out) {
    __shared__ float s_h[128 * 65];
    __shared__ float s_w[64 * 18];   /* [i][j(0..8)][o(0..1)] */
    int tid = threadIdx.x;
    for (int t = tid; t < 64 * 18; t += 128) {
        int i = t / 18, rem = t % 18, j = rem >> 1, o = rem & 1;
        s_w[t] = (j < 8) ? ks2[((size_t)o * 64 + i) * 8 + j] : kb2[o * 64 + i];
    }
    int n0 = blockIdx.x * 128;
    for (int t = tid; t < 128 * 64; t += 128) {
        int r = t >> 6, c = t & 63;
        int gn = n0 + r;
        s_h[r * 65 + c] = (gn < N_NODES) ? g_hk[(size_t)gn * 64 + c] : 0.0f;
    }
    __syncthreads();
    int gn = n0 + tid;
    if (gn >= N_NODES) return;
    float o0 = 0.0f, o1 = 0.0f;
    for (int i = 0; i < 64; i++) {
        float x = s_h[tid * 65 + i];
        float b[8];
        bspline_basis(x, b);
        float v8 = silu_f(x);
        const float* w = &s_w[i * 18];
#pragma unroll
        for (int j = 0; j < 8; j++) {
            o0 = fmaf(b[j], w[j * 2 + 0], o0);
            o1 = fmaf(b[j], w[j * 2 + 1], o1);
        }
        o0 = fmaf(v8, w[16], o0);
        o1 = fmaf(v8, w[17], o1);
    }
    out[(size_t)gn * 2 + 0] = o0;
    out[(size_t)gn * 2 + 1] = o1;
}

/* ------------------------------------------------------------------ */
extern "C" void kernel_launch(void* const* d_in, const int* in_sizes, int n_in,
                              void* d_out, int out_size) {
    const float* x   = (const float*)d_in[0];
    const int*   e   = (const int*)d_in[1];
    const float* W1l = (const float*)d_in[2];
    const float* b1  = (const float*)d_in[3];
    const float* W1r = (const float*)d_in[4];
    const float* W2l = (const float*)d_in[5];
    const float* b2  = (const float*)d_in[6];
    const float* W2r = (const float*)d_in[7];
    const float* kb1 = (const float*)d_in[8];
    const float* ks1 = (const float*)d_in[9];
    const float* kb2 = (const float*)d_in[10];
    const float* ks2 = (const float*)d_in[11];
    float* out = (float*)d_out;

    (void)in_sizes; (void)n_in; (void)out_size;

    const int EB  = (N_EDGES + 255) / 256;
    const int NBK = (N_NODES + 255) / 256;

    detect0_kernel<<<1, 32>>>();
    detect_kernel<<<8, 256>>>(e);
    detect2_kernel<<<1, 32>>>();
    init_kernel<<<NBK, 256>>>();
    convert_kernel<<<EB, 256>>>(e);
    hist_kernel<<<EB, 256>>>();
    scan_kernel<<<1, 1024>>>();
    scatter_kernel<<<EB, 256>>>();
    prep_w_kernel<<<(HID * HID + 255) / 256, 256>>>(W1l, W1r, W2l, W2r);
    prep_wc_kernel<<<(KAN_HID * K1W + 255) / 256, 256>>>(kb1, ks1);
    xcnv_kernel<<<(N_NODES * 64 + 255) / 256, 256>>>(x);

    /* layer 1 */
    agg_kernel<<<(N_NODES + 7) / 8, 256>>>(x, 0);
    conv_mma_kernel<<<dim3((N_NODES + 127) / 128, 2), 256>>>(b1, 0);
    /* layer 2 */
    agg_kernel<<<(N_NODES + 7) / 8, 256>>>(x, 1);
    conv_mma_kernel<<<dim3((N_NODES + 127) / 128, 2), 256>>>(b2, 1);
    /* KAN 1 */
    phi_kernel<<<(N_NODES * 64 + 255) / 256, 256>>>();
    kan1_mma_kernel<<<(N_NODES + 127) / 128, 256>>>();
    /* KAN 2 */
    kan2_kernel<<<(N_NODES + 127) / 128, 128>>>(kb2, ks2, out);
}